// round 2
// baseline (speedup 1.0000x reference)
#include <cuda_runtime.h>
#include <cstdint>
#include <cstddef>

#define NB 8
#define NN 2048
#define FD 128
#define KC 32
#define APAD 36
#define BPAD 132
#define A_TILE_F (128 * APAD)          // 4608 floats
#define B_TILE_F (KC * BPAD)           // 4224 floats
#define STAGE_F  (A_TILE_F + B_TILE_F) // 8832 floats
#define GEMM_SMEM (2 * STAGE_F * 4)    // 70656 bytes

// ---------------- device scratch (no cudaMalloc allowed) ----------------
__device__ float g_dis[NB * NN];
__device__ float g_Hs [NB * NN * FD];   // dis[m]*lrelu(XW+b), tf32-rounded, row-major [b*N+m][f]
__device__ float g_X1 [NB * NN * FD];   // layer-1 output
__device__ float g_X2 [NB * NN * FD];   // layer-2 output
__device__ float g_Wr [3 * FD * FD];    // tf32-rounded weights, row-major [k][n]

// ---------------- helpers ----------------
__device__ __forceinline__ uint32_t cvt_rna(float x) {
    uint32_t r;
    asm("cvt.rna.tf32.f32 %0, %1;" : "=r"(r) : "f"(x));
    return r;
}

__device__ __forceinline__ void mma8(float* c, const uint32_t* a, const uint32_t* b) {
    asm volatile(
        "mma.sync.aligned.m16n8k8.row.col.f32.tf32.tf32.f32 "
        "{%0,%1,%2,%3}, {%4,%5,%6,%7}, {%8,%9}, {%0,%1,%2,%3};"
        : "+f"(c[0]), "+f"(c[1]), "+f"(c[2]), "+f"(c[3])
        : "r"(a[0]), "r"(a[1]), "r"(a[2]), "r"(a[3]), "r"(b[0]), "r"(b[1]));
}

__device__ __forceinline__ void cp16(uint32_t smem_dst, const float* gsrc) {
    asm volatile("cp.async.cg.shared.global [%0], [%1], 16;" :: "r"(smem_dst), "l"(gsrc));
}

// ---------------- prep kernels ----------------
__global__ void k_dis(const float* __restrict__ adj) {
    __shared__ float red[8];
    int row = blockIdx.x;                        // 0..NB*NN-1
    const float4* p = (const float4*)(adj + (size_t)row * NN);
    float s = 0.f;
    for (int i = threadIdx.x; i < NN / 4; i += 256) {
        float4 v = p[i];
        s += (v.x + v.y) + (v.z + v.w);
    }
    #pragma unroll
    for (int o = 16; o > 0; o >>= 1) s += __shfl_xor_sync(0xffffffffu, s, o);
    if ((threadIdx.x & 31) == 0) red[threadIdx.x >> 5] = s;
    __syncthreads();
    if (threadIdx.x < 8) {
        s = red[threadIdx.x];
        #pragma unroll
        for (int o = 4; o > 0; o >>= 1) s += __shfl_xor_sync(0xffu, s, o);
        if (threadIdx.x == 0) g_dis[row] = (s > 0.f) ? rsqrtf(s) : 0.f;
    }
}

__global__ void k_roundW(const float* __restrict__ W1, const float* __restrict__ W2,
                         const float* __restrict__ W3) {
    int i = blockIdx.x * 256 + threadIdx.x;      // 0..3*16384-1
    const float* W = (i < FD * FD) ? W1 : (i < 2 * FD * FD ? W2 : W3);
    int j = i & (FD * FD - 1);
    g_Wr[i] = __uint_as_float(cvt_rna(W[j]));
}

// ---------------- unified GEMM ----------------
// MODE 0 (small): C = X(16384x128) @ Wr_l(128x128); epi: lrelu(+bias), *dis, rna -> g_Hs
// MODE 1 (big):   per batch C = adj(2048x2048) @ Hs_b(2048x128); epi: *dis (+resid) -> out
template <int MODE>
__global__ __launch_bounds__(256, 1) void k_gemm(
    const float* __restrict__ Xext, const float* __restrict__ adj,
    const float* __restrict__ bias, float* __restrict__ outext, int layer, int K)
{
    extern __shared__ float sm[];
    int tid = threadIdx.x, lane = tid & 31, warp = tid >> 5;
    int warpM = (warp & 3) * 32, warpN = (warp >> 2) * 64;

    const float* A;
    const float* B;
    float* C;
    const float* resid = nullptr;
    int lda, grow;

    if (MODE == 1) {
        int b = blockIdx.y;
        grow = b * NN + blockIdx.x * 128;
        lda = NN;
        A = adj + (size_t)grow * NN;
        B = g_Hs + (size_t)b * NN * FD;
        C = (layer == 0) ? g_X1 : (layer == 1 ? g_X2 : outext);
        if (layer == 1) resid = g_X1;
    } else {
        grow = blockIdx.x * 128;
        lda = FD;
        const float* Xin = (layer == 0) ? Xext : (layer == 1 ? g_X1 : g_X2);
        A = Xin + (size_t)grow * FD;
        B = g_Wr + layer * FD * FD;
        C = g_Hs;
    }

    float acc[2][8][4];
    #pragma unroll
    for (int mt = 0; mt < 2; mt++)
        #pragma unroll
        for (int nt = 0; nt < 8; nt++)
            #pragma unroll
            for (int i = 0; i < 4; i++) acc[mt][nt][i] = 0.f;

    // --- async tile loader ---
    auto issue = [&](int stage, int kbase) {
        float* as = sm + stage * STAGE_F;
        float* bs = as + A_TILE_F;
        uint32_t as_u = (uint32_t)__cvta_generic_to_shared(as);
        uint32_t bs_u = (uint32_t)__cvta_generic_to_shared(bs);
        #pragma unroll
        for (int j = 0; j < 4; j++) {                 // A: 128x32 floats
            int i = tid + 256 * j;
            int r = i >> 3, c = (i & 7) << 2;
            cp16(as_u + (uint32_t)(r * APAD + c) * 4, A + (size_t)r * lda + kbase + c);
        }
        #pragma unroll
        for (int j = 0; j < 4; j++) {                 // B: 32x128 floats
            int i = tid + 256 * j;
            int k = i >> 5, c = (i & 31) << 2;
            cp16(bs_u + (uint32_t)(k * BPAD + c) * 4, B + (size_t)(kbase + k) * FD + c);
        }
        asm volatile("cp.async.commit_group;");
    };

    int nch = K / KC;
    issue(0, 0);
    for (int ch = 0; ch < nch; ch++) {
        int st = ch & 1;
        if (ch + 1 < nch) {
            issue(st ^ 1, (ch + 1) * KC);
            asm volatile("cp.async.wait_group 1;");
        } else {
            asm volatile("cp.async.wait_group 0;");
        }
        __syncthreads();

        float* as = sm + st * STAGE_F;
        float* bs = as + A_TILE_F;
        #pragma unroll
        for (int kk = 0; kk < 4; kk++) {
            int kof = kk * 8;
            uint32_t af[2][4];
            uint32_t bf[8][2];
            #pragma unroll
            for (int mt = 0; mt < 2; mt++) {
                int r0 = warpM + mt * 16 + (lane >> 2);
                int kc = kof + (lane & 3);
                af[mt][0] = cvt_rna(as[r0 * APAD + kc]);
                af[mt][1] = cvt_rna(as[(r0 + 8) * APAD + kc]);
                af[mt][2] = cvt_rna(as[r0 * APAD + kc + 4]);
                af[mt][3] = cvt_rna(as[(r0 + 8) * APAD + kc + 4]);
            }
            #pragma unroll
            for (int nt = 0; nt < 8; nt++) {
                int nc = warpN + nt * 8 + (lane >> 2);
                int kr = kof + (lane & 3);
                bf[nt][0] = __float_as_uint(bs[kr * BPAD + nc]);         // pre-rounded
                bf[nt][1] = __float_as_uint(bs[(kr + 4) * BPAD + nc]);
            }
            #pragma unroll
            for (int mt = 0; mt < 2; mt++)
                #pragma unroll
                for (int nt = 0; nt < 8; nt++)
                    mma8(acc[mt][nt], af[mt], bf[nt]);
        }
        __syncthreads();
    }

    // --- epilogue ---
    #pragma unroll
    for (int mt = 0; mt < 2; mt++) {
        #pragma unroll
        for (int nt = 0; nt < 8; nt++) {
            int r0 = grow + warpM + mt * 16 + (lane >> 2);
            int n0 = warpN + nt * 8 + 2 * (lane & 3);
            #pragma unroll
            for (int i = 0; i < 4; i++) {
                int r = r0 + ((i >= 2) ? 8 : 0);
                int n = n0 + (i & 1);
                float v = acc[mt][nt][i];
                if (MODE == 0) {
                    v += bias[n];
                    v = (v > 0.f) ? v : 0.01f * v;
                    v *= g_dis[r];
                    C[(size_t)r * FD + n] = __uint_as_float(cvt_rna(v));
                } else {
                    v *= g_dis[r];
                    if (resid) v += resid[(size_t)r * FD + n];
                    C[(size_t)r * FD + n] = v;
                }
            }
        }
    }
}

// ---------------- launch ----------------
extern "C" void kernel_launch(void* const* d_in, const int* in_sizes, int n_in,
                              void* d_out, int out_size) {
    (void)in_sizes; (void)n_in; (void)out_size;
    const float* X   = (const float*)d_in[0];
    const float* adj = (const float*)d_in[1];
    const float* W1  = (const float*)d_in[2];
    const float* b1  = (const float*)d_in[3];
    const float* W2  = (const float*)d_in[4];
    const float* b2  = (const float*)d_in[5];
    const float* W3  = (const float*)d_in[6];
    const float* b3  = (const float*)d_in[7];
    float* out = (float*)d_out;

    cudaFuncSetAttribute(k_gemm<0>, cudaFuncAttributeMaxDynamicSharedMemorySize, GEMM_SMEM);
    cudaFuncSetAttribute(k_gemm<1>, cudaFuncAttributeMaxDynamicSharedMemorySize, GEMM_SMEM);

    k_dis<<<NB * NN, 256>>>(adj);
    k_roundW<<<(3 * FD * FD) / 256, 256>>>(W1, W2, W3);

    const float* biases[3] = {b1, b2, b3};
    for (int l = 0; l < 3; l++) {
        k_gemm<0><<<dim3(16384 / 128, 1), 256, GEMM_SMEM>>>(X, adj, biases[l], out, l, FD);
        k_gemm<1><<<dim3(NN / 128, NB), 256, GEMM_SMEM>>>(X, adj, biases[l], out, l, NN);
    }
}